// round 5
// baseline (speedup 1.0000x reference)
#include <cuda_runtime.h>

// Shapes (fixed by the problem)
#define BATCH 1024
#define ISZ   1024
#define NH    8
#define HI    8192      // NH * ISZ
#define FEAT  65536     // HI * 8
#define F4    16384     // FEAT / 4

typedef unsigned long long u64;

// ---- f32x2 packed-math helpers (sm_100+; FFMA2 only via PTX) ----
__device__ __forceinline__ u64 pack2(float a, float b) {
    u64 r; asm("mov.b64 %0, {%1,%2};" : "=l"(r) : "f"(a), "f"(b)); return r;
}
__device__ __forceinline__ u64 fma2(u64 a, u64 b, u64 c) {
    u64 r; asm("fma.rn.f32x2 %0, %1, %2, %3;" : "=l"(r) : "l"(a), "l"(b), "l"(c)); return r;
}
__device__ __forceinline__ void unpack2(u64 v, float& a, float& b) {
    asm("mov.b64 {%0,%1}, %2;" : "=f"(a), "=f"(b) : "l"(v));
}

// -------- device scratch (no allocations allowed) --------
__device__ float4 g_A[8 * F4];       // monomial coeffs, layout [n][f/4], f = hi*8 + k
__device__ float  g_Asum[8 * HI];    // [n][hi]
__device__ float  g_Q[15 * HI];      // [p][hi]
__device__ float  g_B1[8 * ISZ];     // [n][i]  head+scale folded
__device__ float  g_B2[15 * ISZ];    // [p][i]
__device__ float  g_S[2 * BATCH];    // per-row sum / sumsq accumulators

// ============================================================
// Pass 0: fold kernel * poly * Chebyshev-monomial into A, Asum, Q.
// ============================================================
__global__ __launch_bounds__(256) void prep_kernel(
    const float* __restrict__ poly,   // [H, I, M]
    const float* __restrict__ kern)   // [H, I, M, K]
{
    int hi = blockIdx.x * blockDim.x + threadIdx.x;
    if (hi < 2 * BATCH) g_S[hi] = 0.0f;
    if (hi >= HI) return;

    const float C[8][8] = {
        {  1,  0,  0,  0,   0,    0,  0,  0},
        {  0,  1,  0,  0,   0,    0,  0,  0},
        { -1,  0,  2,  0,   0,    0,  0,  0},
        {  0, -3,  0,  4,   0,    0,  0,  0},
        {  1,  0, -8,  0,   8,    0,  0,  0},
        {  0,  5,  0,-20,   0,   16,  0,  0},
        { -1,  0, 18,  0, -48,    0, 32,  0},
        {  0, -7,  0, 56,   0, -112,  0, 64}};

    float p[8];
    float W[8][8];
    {
        const float4* p4 = reinterpret_cast<const float4*>(poly + hi * 8);
        float4 pa = __ldg(p4), pb = __ldg(p4 + 1);
        p[0]=pa.x; p[1]=pa.y; p[2]=pa.z; p[3]=pa.w;
        p[4]=pb.x; p[5]=pb.y; p[6]=pb.z; p[7]=pb.w;
        const float4* k4 = reinterpret_cast<const float4*>(kern + hi * 64);
#pragma unroll
        for (int m = 0; m < 8; m++) {
            float4 wa = __ldg(k4 + 2 * m), wb = __ldg(k4 + 2 * m + 1);
            W[m][0]=wa.x; W[m][1]=wa.y; W[m][2]=wa.z; W[m][3]=wa.w;
            W[m][4]=wb.x; W[m][5]=wb.y; W[m][6]=wb.z; W[m][7]=wb.w;
        }
    }

    float a[8][8];
#pragma unroll
    for (int k = 0; k < 8; k++) {
#pragma unroll
        for (int n = 0; n < 8; n++) {
            float s = 0.0f;
#pragma unroll
            for (int m = 0; m < 8; m++) s = fmaf(W[m][k], C[m][n], s);
            a[k][n] = s * p[k];
        }
    }

#pragma unroll
    for (int n = 0; n < 8; n++) {
        float4 lo  = make_float4(a[0][n], a[1][n], a[2][n], a[3][n]);
        float4 hi4 = make_float4(a[4][n], a[5][n], a[6][n], a[7][n]);
        g_A[n * F4 + hi * 2]     = lo;
        g_A[n * F4 + hi * 2 + 1] = hi4;
    }

#pragma unroll
    for (int n = 0; n < 8; n++) {
        float s = 0.0f;
#pragma unroll
        for (int k = 0; k < 8; k++) s += a[k][n];
        g_Asum[n * HI + hi] = s;
    }

    float q[15];
#pragma unroll
    for (int pp = 0; pp < 15; pp++) q[pp] = 0.0f;
#pragma unroll
    for (int k = 0; k < 8; k++)
#pragma unroll
        for (int n1 = 0; n1 < 8; n1++)
#pragma unroll
            for (int n2 = 0; n2 < 8; n2++)
                q[n1 + n2] = fmaf(a[k][n1], a[k][n2], q[n1 + n2]);
#pragma unroll
    for (int pp = 0; pp < 15; pp++) g_Q[pp * HI + hi] = q[pp];
}

// ============================================================
// Pass 0b: fold head axis + scale powers into per-i coefficients.
// grid = (4, 23): blockIdx.y selects the output coefficient.
// ============================================================
__global__ __launch_bounds__(256) void fold_kernel(
    const float* __restrict__ scale)  // [H, I]
{
    int i = blockIdx.x * 256 + threadIdx.x;  // 0..1023
    int c = blockIdx.y;                      // 0..22
    int deg = (c < 8) ? c : (c - 8);

    float acc = 0.0f;
#pragma unroll
    for (int h = 0; h < NH; h++) {
        int hi = h * ISZ + i;
        float sc = __ldg(&scale[hi]);
        float pw = 1.0f;
        for (int t = 0; t < deg; t++) pw *= sc;
        float coef = (c < 8) ? g_Asum[c * HI + hi] : g_Q[(c - 8) * HI + hi];
        acc = fmaf(coef, pw, acc);
    }
    if (c < 8) g_B1[c * ISZ + i]       = acc;
    else       g_B2[(c - 8) * ISZ + i] = acc;
}

// ============================================================
// Pass 1: per-row sum/sumsq over i, f32x2-packed over batch pairs.
// grid = (4 i-blocks, 32 b-chunks), 256 threads.
// ============================================================
__global__ __launch_bounds__(256) void stats_kernel(
    const float* __restrict__ x)      // [B, I]
{
    __shared__ float red[16 * 256];

    int i = blockIdx.x * 256 + threadIdx.x;  // 0..1023

    u64 p1[8];
#pragma unroll
    for (int n = 0; n < 8; n++) { float v = g_B1[n * ISZ + i]; p1[n] = pack2(v, v); }
    u64 p2[15];
#pragma unroll
    for (int pp = 0; pp < 15; pp++) { float v = g_B2[pp * ISZ + i]; p2[pp] = pack2(v, v); }

    int b0   = blockIdx.y * 32;
    int w    = threadIdx.x >> 5;
    int lane = threadIdx.x & 31;

    for (int tile = 0; tile < 4; tile++) {
        int bt = b0 + tile * 8;
#pragma unroll
        for (int pb = 0; pb < 4; pb++) {      // pair of batch rows
            int r0 = 2 * pb;
            float xa = __ldg(&x[(bt + r0)     * ISZ + i]);
            float xb = __ldg(&x[(bt + r0 + 1) * ISZ + i]);
            u64 xx = pack2(xa, xb);

            u64 s1 = p1[7];
#pragma unroll
            for (int n = 6; n >= 0; n--) s1 = fma2(s1, xx, p1[n]);
            u64 s2 = p2[14];
#pragma unroll
            for (int pp = 13; pp >= 0; pp--) s2 = fma2(s2, xx, p2[pp]);

            float s1a, s1b, s2a, s2b;
            unpack2(s1, s1a, s1b);
            unpack2(s2, s2a, s2b);
            red[(2 * r0)     * 256 + threadIdx.x] = s1a;
            red[(2 * r0 + 1) * 256 + threadIdx.x] = s2a;
            red[(2 * r0 + 2) * 256 + threadIdx.x] = s1b;
            red[(2 * r0 + 3) * 256 + threadIdx.x] = s2b;
        }
        __syncthreads();
#pragma unroll
        for (int s = w; s < 16; s += 8) {
            float v = 0.0f;
#pragma unroll
            for (int j = 0; j < 8; j++) v += red[s * 256 + lane + j * 32];
#pragma unroll
            for (int off = 16; off > 0; off >>= 1)
                v += __shfl_xor_sync(0xFFFFFFFFu, v, off);
            if (lane == 0)
                atomicAdd(&g_S[(s & 1) * BATCH + bt + (s >> 1)], v);
        }
        __syncthreads();
    }
}

// ============================================================
// Pass 2: f32x2 Horner (gamma folded), normalize, stream-write.
// Block covers 128 hi within ONE head -> x pre-scaled at staging.
// grid = (64 f-blocks, 64 b-chunks), 256 threads, 16-row b tiles.
// ============================================================
__global__ __launch_bounds__(256) void emit_kernel(
    const float* __restrict__ x,
    const float* __restrict__ scale,
    const float* __restrict__ gamma,
    const float* __restrict__ beta,
    float* __restrict__ out)
{
    __shared__ float xs[16 * 128];       // pre-scaled x tile
    __shared__ u64   s_rs2[16];          // (rs, rs)
    __shared__ u64   s_nt2[16];          // (-mu*rs, -mu*rs)

    int f4 = blockIdx.x * 256 + threadIdx.x;   // 0..16383
    int h  = blockIdx.x >> 3;                  // head of this block
    int i0 = (blockIdx.x * 128) & (ISZ - 1);   // tile's base i
    int b0 = blockIdx.y * 16;

    // Stage x * scale: 16 rows x 128 floats = 512 float4
    {
        float4* xs4 = reinterpret_cast<float4*>(xs);
        const float4* sc4 = reinterpret_cast<const float4*>(scale + h * ISZ + i0);
#pragma unroll
        for (int t = threadIdx.x; t < 512; t += 256) {
            int bb = t >> 5;
            int c4 = t & 31;
            float4 xv = __ldg(reinterpret_cast<const float4*>(
                                  x + (b0 + bb) * ISZ + i0) + c4);
            float4 s  = __ldg(sc4 + c4);
            xv.x *= s.x; xv.y *= s.y; xv.z *= s.z; xv.w *= s.w;
            xs4[t] = xv;
        }
    }
    // Inline finalize: packed rs / -mu*rs per row
    if (threadIdx.x < 16) {
        const float inv = 1.0f / (float)FEAT;
        int b = b0 + threadIdx.x;
        float mu  = g_S[b] * inv;
        float var = g_S[BATCH + b] * inv - mu * mu;
        float rs  = rsqrtf(var + 1e-5f);
        float nt  = -mu * rs;
        s_rs2[threadIdx.x] = pack2(rs, rs);
        s_nt2[threadIdx.x] = pack2(nt, nt);
    }

    float4 g  = reinterpret_cast<const float4*>(gamma)[f4];
    float4 be = reinterpret_cast<const float4*>(beta)[f4];
    u64 g01  = pack2(g.x,  g.y),  g23  = pack2(g.z,  g.w);
    u64 be01 = pack2(be.x, be.y), be23 = pack2(be.z, be.w);

    // gamma-folded packed coefficients
    u64 c01[8], c23[8];
#pragma unroll
    for (int n = 0; n < 8; n++) {
        float4 cn = g_A[n * F4 + f4];
        c01[n] = pack2(cn.x * g.x, cn.y * g.y);
        c23[n] = pack2(cn.z * g.z, cn.w * g.w);
    }

    __syncthreads();

    int il = threadIdx.x >> 1;                 // local i within tile
    ulonglong2* out2 = reinterpret_cast<ulonglong2*>(out);

#pragma unroll 4
    for (int bb = 0; bb < 16; bb++) {
        float xv = xs[bb * 128 + il];
        u64 xx  = pack2(xv, xv);
        u64 rs2 = s_rs2[bb];
        u64 nt2 = s_nt2[bb];

        u64 y01 = c01[7], y23 = c23[7];
#pragma unroll
        for (int n = 6; n >= 0; n--) {
            y01 = fma2(y01, xx, c01[n]);
            y23 = fma2(y23, xx, c23[n]);
        }

        // o = y*rs + (be - mu*rs*g)
        ulonglong2 v;
        v.x = fma2(y01, rs2, fma2(nt2, g01, be01));
        v.y = fma2(y23, rs2, fma2(nt2, g23, be23));
        __stcs(&out2[(size_t)(b0 + bb) * F4 + f4], v);
    }
}

// ============================================================
extern "C" void kernel_launch(void* const* d_in, const int* in_sizes, int n_in,
                              void* d_out, int out_size)
{
    const float* x     = (const float*)d_in[0];  // [1024, 1024]
    const float* scale = (const float*)d_in[1];  // [8, 1024]
    const float* poly  = (const float*)d_in[2];  // [8, 1024, 8]
    const float* kern  = (const float*)d_in[3];  // [8, 1024, 8, 8]
    const float* gamma = (const float*)d_in[4];  // [65536]
    const float* beta  = (const float*)d_in[5];  // [65536]
    float* out = (float*)d_out;                  // [1024, 65536]

    prep_kernel<<<32, 256>>>(poly, kern);
    fold_kernel<<<dim3(4, 23), 256>>>(scale);
    stats_kernel<<<dim3(4, 32), 256>>>(x);
    emit_kernel<<<dim3(64, 64), 256>>>(x, scale, gamma, beta, out);
}

// round 6
// speedup vs baseline: 1.1049x; 1.1049x over previous
#include <cuda_runtime.h>

// Shapes (fixed by the problem)
#define BATCH 1024
#define ISZ   1024
#define NH    8
#define HI    8192      // NH * ISZ
#define FEAT  65536     // HI * 8
#define F4    16384     // FEAT / 4

typedef unsigned long long u64;

// ---- f32x2 packed-math helpers (sm_100+; FFMA2 only via PTX) ----
__device__ __forceinline__ u64 pack2(float a, float b) {
    u64 r; asm("mov.b64 %0, {%1,%2};" : "=l"(r) : "f"(a), "f"(b)); return r;
}
__device__ __forceinline__ u64 fma2(u64 a, u64 b, u64 c) {
    u64 r; asm("fma.rn.f32x2 %0, %1, %2, %3;" : "=l"(r) : "l"(a), "l"(b), "l"(c)); return r;
}

// -------- device scratch (no allocations allowed) --------
__device__ float4 g_A[8 * F4];       // monomial coeffs, layout [n][f/4], f = hi*8 + k
__device__ float  g_Asum[8 * HI];    // [n][hi]
__device__ float  g_Q[15 * HI];      // [p][hi]
__device__ float  g_B1[8 * ISZ];     // [n][i]  head+scale folded
__device__ float  g_B2[15 * ISZ];    // [p][i]
__device__ float  g_S[2 * BATCH];    // per-row sum / sumsq accumulators

// ============================================================
// Pass 0: fold kernel * poly * Chebyshev-monomial into A, Asum, Q.
// One thread per (hi, k): 64K threads, 256 blocks. 8-lane shfl
// reductions produce Asum and Q. Also zeroes g_S.
// ============================================================
__global__ __launch_bounds__(256) void prep_kernel(
    const float* __restrict__ poly,   // [H, I, M]
    const float* __restrict__ kern)   // [H, I, M, K]
{
    int t  = blockIdx.x * 256 + threadIdx.x;   // 0..65535
    int hi = t >> 3;
    int k  = t & 7;
    if (t < 2 * BATCH) g_S[t] = 0.0f;

    // Chebyshev T_m monomial coefficients C[m][n]
    const float C[8][8] = {
        {  1,  0,  0,  0,   0,    0,  0,  0},
        {  0,  1,  0,  0,   0,    0,  0,  0},
        { -1,  0,  2,  0,   0,    0,  0,  0},
        {  0, -3,  0,  4,   0,    0,  0,  0},
        {  1,  0, -8,  0,   8,    0,  0,  0},
        {  0,  5,  0,-20,   0,   16,  0,  0},
        { -1,  0, 18,  0, -48,    0, 32,  0},
        {  0, -7,  0, 56,   0, -112,  0, 64}};

    float p = __ldg(&poly[hi * 8 + k]);
    float W[8];
#pragma unroll
    for (int m = 0; m < 8; m++)
        W[m] = __ldg(&kern[hi * 64 + m * 8 + k]);

    // a[n] = p * sum_m W[m] * C[m][n]   (this thread's k column)
    float a[8];
#pragma unroll
    for (int n = 0; n < 8; n++) {
        float s = 0.0f;
#pragma unroll
        for (int m = 0; m < 8; m++) s = fmaf(W[m], C[m][n], s);
        a[n] = s * p;
    }

    // A in [n][f] layout, f = hi*8 + k = t  -> perfectly coalesced
    float* Af = reinterpret_cast<float*>(g_A);
#pragma unroll
    for (int n = 0; n < 8; n++) Af[n * FEAT + t] = a[n];

    // Asum[n] = sum over the 8 k-lanes of this hi group
    float s[8];
#pragma unroll
    for (int n = 0; n < 8; n++) s[n] = a[n];
#pragma unroll
    for (int off = 1; off < 8; off <<= 1)
#pragma unroll
        for (int n = 0; n < 8; n++)
            s[n] += __shfl_xor_sync(0xFFFFFFFFu, s[n], off);

    // Q[p] = sum_k sum_{n1+n2=p} a[n1]*a[n2]
    float q[15];
#pragma unroll
    for (int pp = 0; pp < 15; pp++) q[pp] = 0.0f;
#pragma unroll
    for (int n1 = 0; n1 < 8; n1++)
#pragma unroll
        for (int n2 = 0; n2 < 8; n2++)
            q[n1 + n2] = fmaf(a[n1], a[n2], q[n1 + n2]);
#pragma unroll
    for (int off = 1; off < 8; off <<= 1)
#pragma unroll
        for (int pp = 0; pp < 15; pp++)
            q[pp] += __shfl_xor_sync(0xFFFFFFFFu, q[pp], off);

    if (k == 0) {
#pragma unroll
        for (int n = 0; n < 8; n++)  g_Asum[n * HI + hi] = s[n];
#pragma unroll
        for (int pp = 0; pp < 15; pp++) g_Q[pp * HI + hi] = q[pp];
    }
}

// ============================================================
// Pass 0b: fold head axis + scale powers into per-i coefficients.
// grid = (4, 23): blockIdx.y selects the output coefficient.
// ============================================================
__global__ __launch_bounds__(256) void fold_kernel(
    const float* __restrict__ scale)  // [H, I]
{
    int i = blockIdx.x * 256 + threadIdx.x;  // 0..1023
    int c = blockIdx.y;                      // 0..22
    int deg = (c < 8) ? c : (c - 8);

    float acc = 0.0f;
#pragma unroll
    for (int h = 0; h < NH; h++) {
        int hi = h * ISZ + i;
        float sc = __ldg(&scale[hi]);
        float pw = 1.0f;
        for (int t = 0; t < deg; t++) pw *= sc;
        float coef = (c < 8) ? g_Asum[c * HI + hi] : g_Q[(c - 8) * HI + hi];
        acc = fmaf(coef, pw, acc);
    }
    if (c < 8) g_B1[c * ISZ + i]       = acc;
    else       g_B2[(c - 8) * ISZ + i] = acc;
}

// ============================================================
// Pass 1: per-row sum/sumsq over i only (round-4 scalar form).
// grid = (4 i-blocks, 32 b-chunks), 256 threads.
// ============================================================
__global__ __launch_bounds__(256) void stats_kernel(
    const float* __restrict__ x)      // [B, I]
{
    __shared__ float red[16 * 256];

    int i = blockIdx.x * 256 + threadIdx.x;  // 0..1023

    float b1[8];
#pragma unroll
    for (int n = 0; n < 8; n++) b1[n] = g_B1[n * ISZ + i];
    float b2[15];
#pragma unroll
    for (int pp = 0; pp < 15; pp++) b2[pp] = g_B2[pp * ISZ + i];

    int b0   = blockIdx.y * 32;
    int w    = threadIdx.x >> 5;
    int lane = threadIdx.x & 31;

    for (int tile = 0; tile < 4; tile++) {
        int bt = b0 + tile * 8;
#pragma unroll
        for (int bb = 0; bb < 8; bb++) {
            float xv = __ldg(&x[(bt + bb) * ISZ + i]);

            float s1 = b1[7];
#pragma unroll
            for (int n = 6; n >= 0; n--) s1 = fmaf(s1, xv, b1[n]);
            float s2 = b2[14];
#pragma unroll
            for (int pp = 13; pp >= 0; pp--) s2 = fmaf(s2, xv, b2[pp]);

            red[(2 * bb)     * 256 + threadIdx.x] = s1;
            red[(2 * bb + 1) * 256 + threadIdx.x] = s2;
        }
        __syncthreads();
#pragma unroll
        for (int s = w; s < 16; s += 8) {
            float v = 0.0f;
#pragma unroll
            for (int j = 0; j < 8; j++) v += red[s * 256 + lane + j * 32];
#pragma unroll
            for (int off = 16; off > 0; off >>= 1)
                v += __shfl_xor_sync(0xFFFFFFFFu, v, off);
            if (lane == 0)
                atomicAdd(&g_S[(s & 1) * BATCH + bt + (s >> 1)], v);
        }
        __syncthreads();
    }
}

// ============================================================
// Pass 2: f32x2 Horner (gamma folded), normalize, stream-write.
// Block covers 128 hi within ONE head -> x pre-scaled at staging.
// grid = (64 f-blocks, 64 b-chunks), 256 threads, 16-row b tiles.
// ============================================================
__global__ __launch_bounds__(256) void emit_kernel(
    const float* __restrict__ x,
    const float* __restrict__ scale,
    const float* __restrict__ gamma,
    const float* __restrict__ beta,
    float* __restrict__ out)
{
    __shared__ float xs[16 * 128];       // pre-scaled x tile
    __shared__ u64   s_rs2[16];          // (rs, rs)
    __shared__ u64   s_nt2[16];          // (-mu*rs, -mu*rs)

    int f4 = blockIdx.x * 256 + threadIdx.x;   // 0..16383
    int h  = blockIdx.x >> 3;                  // head of this block
    int i0 = (blockIdx.x * 128) & (ISZ - 1);   // tile's base i
    int b0 = blockIdx.y * 16;

    // Stage x * scale: 16 rows x 128 floats = 512 float4
    {
        float4* xs4 = reinterpret_cast<float4*>(xs);
        const float4* sc4 = reinterpret_cast<const float4*>(scale + h * ISZ + i0);
#pragma unroll
        for (int t = threadIdx.x; t < 512; t += 256) {
            int bb = t >> 5;
            int c4 = t & 31;
            float4 xv = __ldg(reinterpret_cast<const float4*>(
                                  x + (b0 + bb) * ISZ + i0) + c4);
            float4 s  = __ldg(sc4 + c4);
            xv.x *= s.x; xv.y *= s.y; xv.z *= s.z; xv.w *= s.w;
            xs4[t] = xv;
        }
    }
    // Inline finalize: packed rs / -mu*rs per row
    if (threadIdx.x < 16) {
        const float inv = 1.0f / (float)FEAT;
        int b = b0 + threadIdx.x;
        float mu  = g_S[b] * inv;
        float var = g_S[BATCH + b] * inv - mu * mu;
        float rs  = rsqrtf(var + 1e-5f);
        float nt  = -mu * rs;
        s_rs2[threadIdx.x] = pack2(rs, rs);
        s_nt2[threadIdx.x] = pack2(nt, nt);
    }

    float4 g  = reinterpret_cast<const float4*>(gamma)[f4];
    float4 be = reinterpret_cast<const float4*>(beta)[f4];
    u64 g01  = pack2(g.x,  g.y),  g23  = pack2(g.z,  g.w);
    u64 be01 = pack2(be.x, be.y), be23 = pack2(be.z, be.w);

    // gamma-folded packed coefficients
    u64 c01[8], c23[8];
#pragma unroll
    for (int n = 0; n < 8; n++) {
        float4 cn = g_A[n * F4 + f4];
        c01[n] = pack2(cn.x * g.x, cn.y * g.y);
        c23[n] = pack2(cn.z * g.z, cn.w * g.w);
    }

    __syncthreads();

    int il = threadIdx.x >> 1;                 // local i within tile
    ulonglong2* out2 = reinterpret_cast<ulonglong2*>(out);

#pragma unroll 4
    for (int bb = 0; bb < 16; bb++) {
        float xv = xs[bb * 128 + il];
        u64 xx  = pack2(xv, xv);
        u64 rs2 = s_rs2[bb];
        u64 nt2 = s_nt2[bb];

        u64 y01 = c01[7], y23 = c23[7];
#pragma unroll
        for (int n = 6; n >= 0; n--) {
            y01 = fma2(y01, xx, c01[n]);
            y23 = fma2(y23, xx, c23[n]);
        }

        // o = y*rs + (be - mu*rs*g)
        ulonglong2 v;
        v.x = fma2(y01, rs2, fma2(nt2, g01, be01));
        v.y = fma2(y23, rs2, fma2(nt2, g23, be23));
        __stcs(&out2[(size_t)(b0 + bb) * F4 + f4], v);
    }
}

// ============================================================
extern "C" void kernel_launch(void* const* d_in, const int* in_sizes, int n_in,
                              void* d_out, int out_size)
{
    const float* x     = (const float*)d_in[0];  // [1024, 1024]
    const float* scale = (const float*)d_in[1];  // [8, 1024]
    const float* poly  = (const float*)d_in[2];  // [8, 1024, 8]
    const float* kern  = (const float*)d_in[3];  // [8, 1024, 8, 8]
    const float* gamma = (const float*)d_in[4];  // [65536]
    const float* beta  = (const float*)d_in[5];  // [65536]
    float* out = (float*)d_out;                  // [1024, 65536]

    prep_kernel<<<256, 256>>>(poly, kern);
    fold_kernel<<<dim3(4, 23), 256>>>(scale);
    stats_kernel<<<dim3(4, 32), 256>>>(x);
    emit_kernel<<<dim3(64, 64), 256>>>(x, scale, gamma, beta, out);
}